// round 2
// baseline (speedup 1.0000x reference)
#include <cuda_runtime.h>
#include <cuda_bf16.h>

// Problem constants
#define BB     2
#define NN     65536
#define CC     256
#define HH     8
#define DD     64
#define SS     64
#define INNERD 512
#define TOKCH  1024   // tokens per CTA
#define TSUB   64     // token subtile

// Device scratch (no allocations allowed)
__device__ __align__(16) float g_Weff[HH][CC][SS];   // folded Wx@Wslice, [h][k][s]
__device__ __align__(16) float g_beff[HH][SS];
__device__ __align__(16) float g_acc[BB * HH * SS * DD];
__device__ __align__(16) float g_norm[BB * HH * SS];

// ---------------------------------------------------------------- zero
__global__ void zero_kernel() {
    int i = blockIdx.x * blockDim.x + threadIdx.x;
    if (i < BB * HH * SS * DD) g_acc[i] = 0.0f;
    if (i < BB * HH * SS)      g_norm[i] = 0.0f;
}

// ------------------------------------------------- precompute Weff/beff
__global__ void precompute_kernel(const float* __restrict__ Wx,
                                  const float* __restrict__ bx,
                                  const float* __restrict__ Wslice,
                                  const float* __restrict__ bslice) {
    int m = blockIdx.x;
    int s = threadIdx.x;  // 0..63
    if (m < HH * CC) {
        int h = m / CC, k = m % CC;
        float a = 0.0f;
#pragma unroll 16
        for (int d = 0; d < DD; d++)
            a += Wx[(size_t)k * INNERD + h * DD + d] * Wslice[d * SS + s];
        g_Weff[h][k][s] = a;
    } else {
        for (int h = 0; h < HH; h++) {
            float a = bslice[s];
            for (int d = 0; d < DD; d++)
                a += bx[h * DD + d] * Wslice[d * SS + s];
            g_beff[h][s] = a;
        }
    }
}

// ---------------------------------------------------------------- main
struct SmemLayout {
    float xs[64][68];     // x slab, transposed: [k][tok]  (pad 68 for banks, 16B-aligned rows)
    float we[64][64];     // Weff slab [k][s]
    float wf[64][64];     // Wfx  slab [k][d]
    float wbuf[64][68];   // softmax weights [tok][s]
    float fbuf[64][68];   // fx tile [tok][d]
    float snorm[64];
};

extern __shared__ unsigned char smem_raw[];

__global__ __launch_bounds__(256, 2) void fused_main(
    const float* __restrict__ x,
    const float* __restrict__ Wfx,
    const float* __restrict__ bfx,
    const float* __restrict__ temperature)
{
    SmemLayout& sm = *reinterpret_cast<SmemLayout*>(smem_raw);
    const int chunk = blockIdx.x;
    const int h     = blockIdx.y;
    const int b     = blockIdx.z;
    const int t  = threadIdx.x;
    const int ty = t >> 4;     // 0..15 -> token rows (GEMM1/2) / s rows (GEMM3)
    const int tx = t & 15;     // 0..15 -> s/d columns

    float acc[4][4] = {};      // output tile accumulator over (s, d)
    float nacc[4]   = {};      // per-s weight-mass accumulator

    float be4[4], bf4[4];
#pragma unroll
    for (int j = 0; j < 4; j++) {
        be4[j] = g_beff[h][tx * 4 + j];
        bf4[j] = bfx[h * DD + tx * 4 + j];
    }
    float tmp = temperature[h];
    tmp = fminf(fmaxf(tmp, 0.5f), 5.0f);
    const float invt = __fdividef(1.0f, tmp);

    if (t < 64) sm.snorm[t] = 0.0f;

    const size_t xbase = ((size_t)b * NN + (size_t)chunk * TOKCH) * CC;

    for (int st = 0; st < TOKCH / TSUB; st++) {
        float proj[4][4] = {};
        float fxt[4][4]  = {};
        const size_t xsub = xbase + (size_t)st * TSUB * CC;

        for (int ks = 0; ks < CC; ks += 64) {
            // ---- stage x (transposed), Weff slab, Wfx slab ----
#pragma unroll
            for (int rr = 0; rr < 4; rr++) {
                int row = ty + rr * 16;  // token row / k row
                float4 v = *reinterpret_cast<const float4*>(
                    &x[xsub + (size_t)row * CC + ks + tx * 4]);
                sm.xs[tx * 4 + 0][row] = v.x;
                sm.xs[tx * 4 + 1][row] = v.y;
                sm.xs[tx * 4 + 2][row] = v.z;
                sm.xs[tx * 4 + 3][row] = v.w;
                *reinterpret_cast<float4*>(&sm.we[row][tx * 4]) =
                    *reinterpret_cast<const float4*>(&g_Weff[h][ks + row][tx * 4]);
                *reinterpret_cast<float4*>(&sm.wf[row][tx * 4]) =
                    *reinterpret_cast<const float4*>(
                        &Wfx[(size_t)(ks + row) * INNERD + h * DD + tx * 4]);
            }
            __syncthreads();

            // ---- dual GEMM: proj += x@Weff, fxt += x@Wfx (shared A operand) ----
#pragma unroll 8
            for (int k = 0; k < 64; k++) {
                float4 a = *reinterpret_cast<float4*>(&sm.xs[k][ty * 4]);
                float4 u = *reinterpret_cast<float4*>(&sm.we[k][tx * 4]);
                float4 v = *reinterpret_cast<float4*>(&sm.wf[k][tx * 4]);
                float av[4] = {a.x, a.y, a.z, a.w};
                float uv[4] = {u.x, u.y, u.z, u.w};
                float vv[4] = {v.x, v.y, v.z, v.w};
#pragma unroll
                for (int i = 0; i < 4; i++) {
#pragma unroll
                    for (int j = 0; j < 4; j++) {
                        proj[i][j] += av[i] * uv[j];
                        fxt[i][j]  += av[i] * vv[j];
                    }
                }
            }
            __syncthreads();
        }

        // ---- temperature-scaled softmax over s (row = token, spread over 16 tx lanes) ----
#pragma unroll
        for (int i = 0; i < 4; i++) {
            float p[4];
#pragma unroll
            for (int j = 0; j < 4; j++) p[j] = (proj[i][j] + be4[j]) * invt;
            float m = fmaxf(fmaxf(p[0], p[1]), fmaxf(p[2], p[3]));
#pragma unroll
            for (int off = 1; off < 16; off <<= 1)
                m = fmaxf(m, __shfl_xor_sync(0xffffffffu, m, off, 16));
            float e[4];
            float ssum = 0.0f;
#pragma unroll
            for (int j = 0; j < 4; j++) { e[j] = __expf(p[j] - m); ssum += e[j]; }
#pragma unroll
            for (int off = 1; off < 16; off <<= 1)
                ssum += __shfl_xor_sync(0xffffffffu, ssum, off, 16);
            float r = __fdividef(1.0f, ssum);
            float4 wv;
            wv.x = e[0] * r; wv.y = e[1] * r; wv.z = e[2] * r; wv.w = e[3] * r;
            nacc[0] += wv.x; nacc[1] += wv.y; nacc[2] += wv.z; nacc[3] += wv.w;
            *reinterpret_cast<float4*>(&sm.wbuf[ty * 4 + i][tx * 4]) = wv;
            float4 fv;
            fv.x = fxt[i][0] + bf4[0]; fv.y = fxt[i][1] + bf4[1];
            fv.z = fxt[i][2] + bf4[2]; fv.w = fxt[i][3] + bf4[3];
            *reinterpret_cast<float4*>(&sm.fbuf[ty * 4 + i][tx * 4]) = fv;
        }
        __syncthreads();

        // ---- rank-64 update: acc[s][d] += w^T @ fx over this token subtile ----
#pragma unroll 8
        for (int kk = 0; kk < 64; kk++) {
            float4 wv = *reinterpret_cast<float4*>(&sm.wbuf[kk][ty * 4]);
            float4 fv = *reinterpret_cast<float4*>(&sm.fbuf[kk][tx * 4]);
            float wa[4] = {wv.x, wv.y, wv.z, wv.w};
            float fa[4] = {fv.x, fv.y, fv.z, fv.w};
#pragma unroll
            for (int i = 0; i < 4; i++) {
#pragma unroll
                for (int j = 0; j < 4; j++) acc[i][j] += wa[i] * fa[j];
            }
        }
        __syncthreads();
    }

    // ---- per-CTA reductions -> global atomics ----
#pragma unroll
    for (int j = 0; j < 4; j++) atomicAdd(&sm.snorm[tx * 4 + j], nacc[j]);
    __syncthreads();
    if (t < 64) atomicAdd(&g_norm[(b * HH + h) * SS + t], sm.snorm[t]);

    const int obase = ((b * HH + h) * SS + ty * 4) * DD + tx * 4;
#pragma unroll
    for (int i = 0; i < 4; i++) {
#pragma unroll
        for (int j = 0; j < 4; j++)
            atomicAdd(&g_acc[obase + i * DD + j], acc[i][j]);
    }
}

// ------------------------------------------------------------ finalize
__global__ void finalize_kernel(float* __restrict__ out) {
    int i = blockIdx.x * blockDim.x + threadIdx.x;
    if (i < BB * HH * SS * DD)
        out[i] = g_acc[i] / (g_norm[i >> 6] + 0.01f);
}

// -------------------------------------------------------------- launch
extern "C" void kernel_launch(void* const* d_in, const int* in_sizes, int n_in,
                              void* d_out, int out_size) {
    const float* x           = (const float*)d_in[0];
    const float* Wx          = (const float*)d_in[1];
    const float* bx          = (const float*)d_in[2];
    const float* Wfx         = (const float*)d_in[3];
    const float* bfx         = (const float*)d_in[4];
    const float* Wslice      = (const float*)d_in[5];
    const float* bslice      = (const float*)d_in[6];
    const float* temperature = (const float*)d_in[7];
    float* out = (float*)d_out;

    cudaFuncSetAttribute(fused_main, cudaFuncAttributeMaxDynamicSharedMemorySize,
                         (int)sizeof(SmemLayout));

    zero_kernel<<<(BB * HH * SS * DD + 255) / 256, 256>>>();
    precompute_kernel<<<HH * CC + 1, 64>>>(Wx, bx, Wslice, bslice);
    fused_main<<<dim3(NN / TOKCH, HH, BB), 256, sizeof(SmemLayout)>>>(
        x, Wfx, bfx, temperature);
    finalize_kernel<<<(BB * HH * SS * DD + 255) / 256, 256>>>(out);
}

// round 3
// speedup vs baseline: 1.0251x; 1.0251x over previous
#include <cuda_runtime.h>
#include <cuda_bf16.h>

// Problem constants
#define BB     2
#define NN     65536
#define CC     256
#define HH     8
#define DD     64
#define SS     64
#define INNERD 512
#define TOKCH  1024   // tokens per CTA
#define TSUB   64     // token subtile

// Device scratch (no allocations allowed)
__device__ __align__(16) float g_Weff[HH][CC][SS];   // folded Wx@Wslice, [h][k][s]
__device__ __align__(16) float g_beff[HH][SS];
__device__ __align__(16) float g_acc[BB * HH * SS * DD];
__device__ __align__(16) float g_norm[BB * HH * SS];

// ---- packed f32x2 helpers (FFMA2 — only reachable via PTX) ----
__device__ __forceinline__ unsigned long long bcast2(float v) {
    unsigned long long r;
    asm("mov.b64 %0, {%1, %1};" : "=l"(r) : "f"(v));
    return r;
}
__device__ __forceinline__ void fma2(unsigned long long& d,
                                     unsigned long long a,
                                     unsigned long long b) {
    asm("fma.rn.f32x2 %0, %1, %2, %0;" : "+l"(d) : "l"(a), "l"(b));
}
__device__ __forceinline__ void unpack2(unsigned long long v, float& lo, float& hi) {
    asm("mov.b64 {%0, %1}, %2;" : "=f"(lo), "=f"(hi) : "l"(v));
}

// ---------------------------------------------------------------- zero
__global__ void zero_kernel() {
    int i = blockIdx.x * blockDim.x + threadIdx.x;
    if (i < BB * HH * SS * DD) g_acc[i] = 0.0f;
    if (i < BB * HH * SS)      g_norm[i] = 0.0f;
}

// ------------------------------------------------- precompute Weff/beff
__global__ void precompute_kernel(const float* __restrict__ Wx,
                                  const float* __restrict__ bx,
                                  const float* __restrict__ Wslice,
                                  const float* __restrict__ bslice) {
    int m = blockIdx.x;
    int s = threadIdx.x;  // 0..63
    if (m < HH * CC) {
        int h = m / CC, k = m % CC;
        float a = 0.0f;
#pragma unroll 16
        for (int d = 0; d < DD; d++)
            a += Wx[(size_t)k * INNERD + h * DD + d] * Wslice[d * SS + s];
        g_Weff[h][k][s] = a;
    } else {
        for (int h = 0; h < HH; h++) {
            float a = bslice[s];
            for (int d = 0; d < DD; d++)
                a += bx[h * DD + d] * Wslice[d * SS + s];
            g_beff[h][s] = a;
        }
    }
}

// ---------------------------------------------------------------- main
struct SmemLayout {
    float xs[64][68];     // x slab, transposed: [k][tok]  (pad 68 for banks, 16B-aligned rows)
    float we[64][64];     // Weff slab [k][s]
    float wf[64][64];     // Wfx  slab [k][d]
    float wbuf[64][68];   // softmax weights [tok][s]
    float fbuf[64][68];   // fx tile [tok][d]
    float snorm[64];
};

extern __shared__ unsigned char smem_raw[];

__global__ __launch_bounds__(256, 2) void fused_main(
    const float* __restrict__ x,
    const float* __restrict__ Wfx,
    const float* __restrict__ bfx,
    const float* __restrict__ temperature)
{
    SmemLayout& sm = *reinterpret_cast<SmemLayout*>(smem_raw);
    const int chunk = blockIdx.x;
    const int h     = blockIdx.y;
    const int b     = blockIdx.z;
    const int t  = threadIdx.x;
    const int ty = t >> 4;     // 0..15 -> token rows (GEMM1/2) / s rows (GEMM3)
    const int tx = t & 15;     // 0..15 -> s/d columns (pairs j01, j23)

    unsigned long long acc2[4][2] = {};   // packed (s, d-pair) accumulators
    float nacc[4] = {};

    float be4[4], bf4[4];
#pragma unroll
    for (int j = 0; j < 4; j++) {
        be4[j] = g_beff[h][tx * 4 + j];
        bf4[j] = bfx[h * DD + tx * 4 + j];
    }
    float tmp = temperature[h];
    tmp = fminf(fmaxf(tmp, 0.5f), 5.0f);
    const float invt = __fdividef(1.0f, tmp);

    if (t < 64) sm.snorm[t] = 0.0f;

    const size_t xbase = ((size_t)b * NN + (size_t)chunk * TOKCH) * CC;

    for (int st = 0; st < TOKCH / TSUB; st++) {
        unsigned long long proj2[4][2] = {};
        unsigned long long fxt2[4][2]  = {};
        const size_t xsub = xbase + (size_t)st * TSUB * CC;

        for (int ks = 0; ks < CC; ks += 64) {
            // ---- stage x (transposed), Weff slab, Wfx slab ----
#pragma unroll
            for (int rr = 0; rr < 4; rr++) {
                int row = ty + rr * 16;  // token row / k row
                float4 v = *reinterpret_cast<const float4*>(
                    &x[xsub + (size_t)row * CC + ks + tx * 4]);
                sm.xs[tx * 4 + 0][row] = v.x;
                sm.xs[tx * 4 + 1][row] = v.y;
                sm.xs[tx * 4 + 2][row] = v.z;
                sm.xs[tx * 4 + 3][row] = v.w;
                *reinterpret_cast<float4*>(&sm.we[row][tx * 4]) =
                    *reinterpret_cast<const float4*>(&g_Weff[h][ks + row][tx * 4]);
                *reinterpret_cast<float4*>(&sm.wf[row][tx * 4]) =
                    *reinterpret_cast<const float4*>(
                        &Wfx[(size_t)(ks + row) * INNERD + h * DD + tx * 4]);
            }
            __syncthreads();

            // ---- dual GEMM via FFMA2: proj += x@Weff, fxt += x@Wfx ----
#pragma unroll 8
            for (int k = 0; k < 64; k++) {
                float4 a = *reinterpret_cast<float4*>(&sm.xs[k][ty * 4]);
                ulonglong2 u = *reinterpret_cast<ulonglong2*>(&sm.we[k][tx * 4]);
                ulonglong2 v = *reinterpret_cast<ulonglong2*>(&sm.wf[k][tx * 4]);
                unsigned long long av[4] = {bcast2(a.x), bcast2(a.y),
                                            bcast2(a.z), bcast2(a.w)};
#pragma unroll
                for (int i = 0; i < 4; i++) {
                    fma2(proj2[i][0], av[i], u.x);
                    fma2(proj2[i][1], av[i], u.y);
                    fma2(fxt2[i][0],  av[i], v.x);
                    fma2(fxt2[i][1],  av[i], v.y);
                }
            }
            __syncthreads();
        }

        // ---- temperature-scaled softmax over s (row = token, 16 tx lanes) ----
#pragma unroll
        for (int i = 0; i < 4; i++) {
            float p[4];
            unpack2(proj2[i][0], p[0], p[1]);
            unpack2(proj2[i][1], p[2], p[3]);
#pragma unroll
            for (int j = 0; j < 4; j++) p[j] = (p[j] + be4[j]) * invt;
            float m = fmaxf(fmaxf(p[0], p[1]), fmaxf(p[2], p[3]));
#pragma unroll
            for (int off = 1; off < 16; off <<= 1)
                m = fmaxf(m, __shfl_xor_sync(0xffffffffu, m, off, 16));
            float e[4];
            float ssum = 0.0f;
#pragma unroll
            for (int j = 0; j < 4; j++) { e[j] = __expf(p[j] - m); ssum += e[j]; }
#pragma unroll
            for (int off = 1; off < 16; off <<= 1)
                ssum += __shfl_xor_sync(0xffffffffu, ssum, off, 16);
            float r = __fdividef(1.0f, ssum);
            float4 wv;
            wv.x = e[0] * r; wv.y = e[1] * r; wv.z = e[2] * r; wv.w = e[3] * r;
            nacc[0] += wv.x; nacc[1] += wv.y; nacc[2] += wv.z; nacc[3] += wv.w;
            *reinterpret_cast<float4*>(&sm.wbuf[ty * 4 + i][tx * 4]) = wv;
            float f0, f1, f2, f3;
            unpack2(fxt2[i][0], f0, f1);
            unpack2(fxt2[i][1], f2, f3);
            float4 fv;
            fv.x = f0 + bf4[0]; fv.y = f1 + bf4[1];
            fv.z = f2 + bf4[2]; fv.w = f3 + bf4[3];
            *reinterpret_cast<float4*>(&sm.fbuf[ty * 4 + i][tx * 4]) = fv;
        }
        __syncthreads();

        // ---- rank-64 update via FFMA2: acc[s][d] += w^T @ fx ----
#pragma unroll 8
        for (int kk = 0; kk < 64; kk++) {
            float4 wv = *reinterpret_cast<float4*>(&sm.wbuf[kk][ty * 4]);
            ulonglong2 fv = *reinterpret_cast<ulonglong2*>(&sm.fbuf[kk][tx * 4]);
            unsigned long long wa[4] = {bcast2(wv.x), bcast2(wv.y),
                                        bcast2(wv.z), bcast2(wv.w)};
#pragma unroll
            for (int i = 0; i < 4; i++) {
                fma2(acc2[i][0], wa[i], fv.x);
                fma2(acc2[i][1], wa[i], fv.y);
            }
        }
        __syncthreads();
    }

    // ---- per-CTA reductions -> global atomics ----
#pragma unroll
    for (int j = 0; j < 4; j++) atomicAdd(&sm.snorm[tx * 4 + j], nacc[j]);
    __syncthreads();
    if (t < 64) atomicAdd(&g_norm[(b * HH + h) * SS + t], sm.snorm[t]);

    const int obase = ((b * HH + h) * SS + ty * 4) * DD + tx * 4;
#pragma unroll
    for (int i = 0; i < 4; i++) {
        float a0, a1, a2, a3;
        unpack2(acc2[i][0], a0, a1);
        unpack2(acc2[i][1], a2, a3);
        atomicAdd(&g_acc[obase + i * DD + 0], a0);
        atomicAdd(&g_acc[obase + i * DD + 1], a1);
        atomicAdd(&g_acc[obase + i * DD + 2], a2);
        atomicAdd(&g_acc[obase + i * DD + 3], a3);
    }
}

// ------------------------------------------------------------ finalize
__global__ void finalize_kernel(float* __restrict__ out) {
    int i = blockIdx.x * blockDim.x + threadIdx.x;
    if (i < BB * HH * SS * DD)
        out[i] = g_acc[i] / (g_norm[i >> 6] + 0.01f);
}

// -------------------------------------------------------------- launch
extern "C" void kernel_launch(void* const* d_in, const int* in_sizes, int n_in,
                              void* d_out, int out_size) {
    const float* x           = (const float*)d_in[0];
    const float* Wfx         = (const float*)d_in[3];
    const float* bfx         = (const float*)d_in[4];
    const float* Wx          = (const float*)d_in[1];
    const float* bx          = (const float*)d_in[2];
    const float* Wslice      = (const float*)d_in[5];
    const float* bslice      = (const float*)d_in[6];
    const float* temperature = (const float*)d_in[7];
    float* out = (float*)d_out;

    cudaFuncSetAttribute(fused_main, cudaFuncAttributeMaxDynamicSharedMemorySize,
                         (int)sizeof(SmemLayout));

    zero_kernel<<<(BB * HH * SS * DD + 255) / 256, 256>>>();
    precompute_kernel<<<HH * CC + 1, 64>>>(Wx, bx, Wslice, bslice);
    fused_main<<<dim3(NN / TOKCH, HH, BB), 256, sizeof(SmemLayout)>>>(
        x, Wfx, bfx, temperature);
    finalize_kernel<<<(BB * HH * SS * DD + 255) / 256, 256>>>(out);
}